// round 12
// baseline (speedup 1.0000x reference)
#include <cuda_runtime.h>
#include <cuda_bf16.h>
#include <cstdint>

// ---------------------------------------------------------------------------
// Problem geometry
// ---------------------------------------------------------------------------
#define M_DIM 16384              // 4 * 4096 rows of x
#define K_DIM 4096
#define N_DIM 11008
#define W_ELEMS (N_DIM * K_DIM)  // 45088768
#define X_ELEMS (M_DIM * K_DIM)  // 67108864

// GEMM tiling (bf16): CTA 128x128, warp tile 32x64, BK=64
#define BM 128
#define BN 128
#define BK 64
#define NUM_KITER (K_DIM / BK)     // 64
#define N_TILES (N_DIM / BN)       // 86
#define M_TILES (M_DIM / BM)       // 128
#define GROUP_M 8

#define ROW_BYTES 128                           // BK * 2 (bf16)
#define ROW_PAD 144                             // 128B data + 16B pad (conflict-free)
#define A_STAGE_BYTES (BM * ROW_PAD)            // 18432
#define B_STAGE_BYTES (BN * ROW_PAD)            // 18432
#define STAGE_BYTES (A_STAGE_BYTES + B_STAGE_BYTES)
#define STAGES 3
#define MBAR_BYTES 64
#define SMEM_BYTES (STAGES * STAGE_BYTES + MBAR_BYTES)  // 110656 (2 CTAs/SM)

#define QW_BLOCKS 4096

// ---------------------------------------------------------------------------
// Device scratch (allocation-free rule: __device__ globals)
// ---------------------------------------------------------------------------
__device__ __align__(1024) __nv_bfloat16 g_qw[W_ELEMS];  // ternary {-1,0,1}
__device__ __align__(1024) __nv_bfloat16 g_qx[X_ELEMS];  // integers [-128,127]
__device__ float g_row_scale[M_DIM];                     // gamma_x[m]*gamma_w/127
__device__ float g_partial[1024];

// ---------------------------------------------------------------------------
// PTX helpers (sm_80-class baseline; no 'a' features)
// ---------------------------------------------------------------------------
#define CP_ASYNC16(smem_u32, gptr) \
    asm volatile("cp.async.cg.shared.global.L2::128B [%0], [%1], 16;" \
                 :: "r"(smem_u32), "l"(gptr) : "memory")

#define CP_ASYNC_MBAR_ARRIVE(mbar) \
    asm volatile("cp.async.mbarrier.arrive.noinc.shared.b64 [%0];" \
                 :: "r"((uint32_t)(mbar)) : "memory")

#define MBARRIER_INIT(mbar, count) \
    asm volatile("mbarrier.init.shared.b64 [%0], %1;" \
                 :: "r"((uint32_t)(mbar)), "r"((uint32_t)(count)) : "memory")

#define MBARRIER_ARRIVE(mbar) \
    asm volatile("mbarrier.arrive.shared.b64 _, [%0];" \
                 :: "r"((uint32_t)(mbar)) : "memory")

#define MBARRIER_WAIT_PARITY(mbar_smem_addr, phase_parity) do {                       \
    uint32_t _mbar = (uint32_t)(mbar_smem_addr);                                      \
    uint32_t _parity = (uint32_t)(phase_parity);                                      \
    uint32_t _done;                                                                   \
    asm volatile(                                                                     \
        "{\n\t"                                                                       \
        ".reg .pred p;\n\t"                                                           \
        "mbarrier.try_wait.parity.acquire.cta.shared::cta.b64 p, [%1], %2;\n\t"       \
        "selp.b32 %0, 1, 0, p;\n\t"                                                   \
        "}"                                                                           \
        : "=r"(_done) : "r"(_mbar), "r"(_parity) : "memory");                         \
    if (!_done) {                                                                     \
        asm volatile(                                                                 \
            "{\n\t"                                                                   \
            ".reg .pred P1;\n\t"                                                      \
            "WAIT_LOOP_%=:\n\t"                                                       \
            "mbarrier.try_wait.parity.acquire.cta.shared::cta.b64 P1, [%0], %1, 0x989680;\n\t" \
            "@P1 bra.uni WAIT_DONE_%=;\n\t"                                           \
            "bra.uni WAIT_LOOP_%=;\n\t"                                               \
            "WAIT_DONE_%=:\n\t"                                                       \
            "}"                                                                       \
            :: "r"(_mbar), "r"(_parity) : "memory");                                  \
    }                                                                                 \
} while (0)

#define LDM_X4(r, addr) \
    asm volatile("ldmatrix.sync.aligned.m8n8.x4.shared.b16 {%0,%1,%2,%3}, [%4];" \
                 : "=r"((r)[0]), "=r"((r)[1]), "=r"((r)[2]), "=r"((r)[3]) \
                 : "r"(addr))

#define MMA_BF16(d, a, b0, b1) \
    asm volatile("mma.sync.aligned.m16n8k16.row.col.f32.bf16.bf16.f32 " \
                 "{%0,%1,%2,%3}, {%4,%5,%6,%7}, {%8,%9}, {%0,%1,%2,%3};" \
                 : "+f"((d)[0]), "+f"((d)[1]), "+f"((d)[2]), "+f"((d)[3]) \
                 : "r"((a)[0]), "r"((a)[1]), "r"((a)[2]), "r"((a)[3]), \
                   "r"(b0), "r"(b1))

// ---------------------------------------------------------------------------
// In-block gamma_w reconstruction (deterministic tree, bit-identical always)
// ---------------------------------------------------------------------------
__device__ __forceinline__ float reduce_gamma(float* sdata) {
    const int t = threadIdx.x;
    float s = g_partial[t] + g_partial[t + 256] + g_partial[t + 512] + g_partial[t + 768];
    sdata[t] = s;
    __syncthreads();
    for (int off = 128; off > 0; off >>= 1) {
        if (t < off) sdata[t] += sdata[t + off];
        __syncthreads();
    }
    float g = sdata[0] / (float)W_ELEMS + 1e-5f;
    __syncthreads();
    return g;
}

// ---------------------------------------------------------------------------
// Kernel 0: per-block partial sums of |W|  (exactly 1024 blocks)
// ---------------------------------------------------------------------------
__global__ void wabs_partial_kernel(const float4* __restrict__ w, int n4) {
    __shared__ float sdata[256];
    float s = 0.f;
    for (int i = blockIdx.x * blockDim.x + threadIdx.x; i < n4; i += gridDim.x * blockDim.x) {
        float4 v = w[i];
        s += fabsf(v.x) + fabsf(v.y) + fabsf(v.z) + fabsf(v.w);
    }
    sdata[threadIdx.x] = s;
    __syncthreads();
    for (int off = 128; off > 0; off >>= 1) {
        if (threadIdx.x < off) sdata[threadIdx.x] += sdata[threadIdx.x + off];
        __syncthreads();
    }
    if (threadIdx.x == 0) g_partial[blockIdx.x] = sdata[0];
}

// ---------------------------------------------------------------------------
// Kernel 1 (fused): blocks [0, QW_BLOCKS) quantize W (ternary bf16);
//                   blocks [QW_BLOCKS, QW_BLOCKS+M_DIM) quantize one x row.
// ---------------------------------------------------------------------------
__global__ void quant_fused_kernel(const float4* __restrict__ w,
                                   const float* __restrict__ x, int w_n4) {
    __shared__ float sdata[256];
    const float gw = reduce_gamma(sdata);
    const int t = threadIdx.x;

    if (blockIdx.x < QW_BLOCKS) {
        __nv_bfloat162* qw2 = (__nv_bfloat162*)g_qw;
        for (int i = blockIdx.x * 256 + t; i < w_n4; i += QW_BLOCKS * 256) {
            float4 v = w[i];
            float q0 = fminf(fmaxf(rintf(v.x / gw), -1.f), 1.f);
            float q1 = fminf(fmaxf(rintf(v.y / gw), -1.f), 1.f);
            float q2 = fminf(fmaxf(rintf(v.z / gw), -1.f), 1.f);
            float q3 = fminf(fmaxf(rintf(v.w / gw), -1.f), 1.f);
            qw2[i * 2]     = __floats2bfloat162_rn(q0, q1);
            qw2[i * 2 + 1] = __floats2bfloat162_rn(q2, q3);
        }
        return;
    }

    const int row = blockIdx.x - QW_BLOCKS;
    const float4* xr = (const float4*)(x + (size_t)row * K_DIM);

    float4 vv[4];
    float m = 0.f;
#pragma unroll
    for (int j = 0; j < 4; ++j) {
        float4 v = xr[t + j * 256];
        vv[j] = v;
        m = fmaxf(m, fmaxf(fmaxf(fabsf(v.x), fabsf(v.y)), fmaxf(fabsf(v.z), fabsf(v.w))));
    }
    sdata[t] = m;
    __syncthreads();
    for (int off = 128; off > 0; off >>= 1) {
        if (t < off) sdata[t] = fmaxf(sdata[t], sdata[t + off]);
        __syncthreads();
    }
    const float gx = sdata[0] + 1e-5f;

    __nv_bfloat162* qr = (__nv_bfloat162*)(g_qx + (size_t)row * K_DIM);
#pragma unroll
    for (int j = 0; j < 4; ++j) {
        float4 v = vv[j];
        float q0 = fminf(fmaxf(rintf((127.f * v.x) / gx), -128.f), 127.f);
        float q1 = fminf(fmaxf(rintf((127.f * v.y) / gx), -128.f), 127.f);
        float q2 = fminf(fmaxf(rintf((127.f * v.z) / gx), -128.f), 127.f);
        float q3 = fminf(fmaxf(rintf((127.f * v.w) / gx), -128.f), 127.f);
        int i = t + j * 256;
        qr[i * 2]     = __floats2bfloat162_rn(q0, q1);
        qr[i * 2 + 1] = __floats2bfloat162_rn(q2, q3);
    }
    if (t == 0) g_row_scale[row] = gx * gw * (1.0f / 127.0f);
}

// ---------------------------------------------------------------------------
// Kernel 2: bf16 GEMM via mma.m16n8k16 (integer-exact).
//   mbarrier producer/consumer pipeline with:
//     - cross-iteration fragment prefetch (FULL wait + next-stage frag load
//       overlap the last MMA block -> no per-iter priming bubble)
//     - early EMPTY release at the last smem read (ks=2) of each stage
//     - elected EMPTY arrivals (count 8, lane 0 per warp)
//   CTA 128x128, 8 warps (4m x 2n), warp tile 32x64, BK=64, 3 stages, 2 CTA/SM.
//   out[m, n] = (sum_k A[m,k]*B[n,k]) * g_row_scale[m]
// ---------------------------------------------------------------------------
__global__ void __launch_bounds__(256, 2)
gemm_bf16(const __nv_bfloat16* __restrict__ A, const __nv_bfloat16* __restrict__ B,
          float* __restrict__ out) {
    extern __shared__ char smem[];
    const uint32_t sb = (uint32_t)__cvta_generic_to_shared(smem);
    const int tid = threadIdx.x;
    const int wid = tid >> 5;
    const int lane = tid & 31;
    const int wm = wid >> 1;   // 0..3 (m)
    const int wn = wid & 1;    // 0..1 (n)

    const uint32_t mb = sb + STAGES * STAGE_BYTES;
#define FULL_BAR(s)  (mb + (uint32_t)(s) * 16u)
#define EMPTY_BAR(s) (mb + (uint32_t)(s) * 16u + 8u)

    if (tid == 0) {
#pragma unroll
        for (int s = 0; s < STAGES; ++s) {
            MBARRIER_INIT(FULL_BAR(s), 256);   // one async arrive per thread
            MBARRIER_INIT(EMPTY_BAR(s), 8);    // one arrive per WARP (lane 0)
        }
    }
    __syncthreads();   // barriers visible before any use (only block sync here)

    // tile mapping with GROUP_M swizzle for L2 reuse
    const int per_group = GROUP_M * N_TILES;
    const int group = blockIdx.x / per_group;
    const int rem = blockIdx.x - group * per_group;
    const int m_tile = group * GROUP_M + (rem % GROUP_M);
    const int n_tile = rem / GROUP_M;

    const char* gA = (const char*)(A + (size_t)(m_tile * BM) * K_DIM);
    const char* gB = (const char*)(B + (size_t)(n_tile * BN) * K_DIM);
    const size_t KROW = (size_t)K_DIM * 2;   // bytes per global row

    const int lrw = tid >> 3;        // base row 0..31
    const int lcc = tid & 7;         // 16B chunk within 128B row

    int p_st = 0, p_ph = 1;          // producer cursor (empty-wait), phase 1

#define PRODUCE(kt) do {                                                            \
    MBARRIER_WAIT_PARITY(EMPTY_BAR(p_st), p_ph);                                    \
    uint32_t abase = sb + (uint32_t)p_st * STAGE_BYTES + lcc * 16;                  \
    uint32_t bbase = abase + A_STAGE_BYTES;                                         \
    const char* ga = gA + (size_t)(kt) * ROW_BYTES + lcc * 16;                      \
    const char* gb = gB + (size_t)(kt) * ROW_BYTES + lcc * 16;                      \
    _Pragma("unroll")                                                               \
    for (int t = 0; t < 4; ++t) {                                                   \
        int row = lrw + t * 32;                                                     \
        CP_ASYNC16(abase + row * ROW_PAD, ga + (size_t)row * KROW);                 \
        CP_ASYNC16(bbase + row * ROW_PAD, gb + (size_t)row * KROW);                 \
    }                                                                               \
    CP_ASYNC_MBAR_ARRIVE(FULL_BAR(p_st));                                           \
    if (++p_st == STAGES) { p_st = 0; p_ph ^= 1; }                                  \
} while (0)

    float acc[2][8][4];
#pragma unroll
    for (int mt = 0; mt < 2; ++mt)
#pragma unroll
        for (int nt = 0; nt < 8; ++nt)
#pragma unroll
            for (int j = 0; j < 4; ++j) acc[mt][nt][j] = 0.f;

    const int lrow = lane & 15;
    const uint32_t lhalf = (uint32_t)(lane >> 4) * 16;
    const uint32_t a_row_off = (uint32_t)(wm * 32 + lrow) * ROW_PAD + lhalf;
    const uint32_t b_row_off = (uint32_t)(wn * 64 + lrow) * ROW_PAD + lhalf;

    uint32_t afr[2][2][4];   // [buf][mt][4]
    uint32_t bfr[2][4][4];   // [buf][np][4]

#define LOAD_FRAGS(base_a, base_b, ks, fb) do {                                     \
    const uint32_t kbyte = (uint32_t)(ks) * 32;                                     \
    _Pragma("unroll")                                                               \
    for (int mt = 0; mt < 2; ++mt)                                                  \
        LDM_X4(afr[fb][mt], (base_a) + a_row_off + (uint32_t)(mt * 16) * ROW_PAD + kbyte); \
    _Pragma("unroll")                                                               \
    for (int np = 0; np < 4; ++np)                                                  \
        LDM_X4(bfr[fb][np], (base_b) + b_row_off + (uint32_t)(np * 16) * ROW_PAD + kbyte); \
} while (0)

#define MMA_BLOCK(fb) do {                                                          \
    _Pragma("unroll")                                                               \
    for (int mt = 0; mt < 2; ++mt)                                                  \
        _Pragma("unroll")                                                           \
        for (int nt = 0; nt < 8; ++nt) {                                            \
            const int np = nt >> 1, sel = nt & 1;                                   \
            MMA_BF16(acc[mt][nt], afr[fb][mt], bfr[fb][np][sel], bfr[fb][np][2 + sel]); \
        }                                                                           \
} while (0)

    // prologue: stages 0,1 produced; stage 0 primed into frag buf0
    PRODUCE(0);
    PRODUCE(1);
    MBARRIER_WAIT_PARITY(FULL_BAR(0), 0);

    uint32_t ab = sb;                    // current consume stage base
    uint32_t bb = sb + A_STAGE_BYTES;
    int e_st = 0;                        // stage index being consumed
    int c_st = 1, c_ph = 0;              // cursor for next FULL wait

    LOAD_FRAGS(ab, bb, 0, 0);

    for (int kk = 0; kk < NUM_KITER; ++kk) {
        if (kk + 2 < NUM_KITER) PRODUCE(kk + 2);

        // ks = 0
        LOAD_FRAGS(ab, bb, 1, 1);
        MMA_BLOCK(0);
        // ks = 1
        LOAD_FRAGS(ab, bb, 2, 0);
        MMA_BLOCK(1);
        // ks = 2  (last smem read of this stage -> release EMPTY early)
        LOAD_FRAGS(ab, bb, 3, 1);
        if (lane == 0) MBARRIER_ARRIVE(EMPTY_BAR(e_st));
        MMA_BLOCK(0);
        // ks = 3  (overlap: wait next FULL + prime its ks=0 frags during MMAs)
        if (kk + 1 < NUM_KITER) {
            MBARRIER_WAIT_PARITY(FULL_BAR(c_st), c_ph);
            const uint32_t nab = sb + (uint32_t)c_st * STAGE_BYTES;
            const uint32_t nbb = nab + A_STAGE_BYTES;
            LOAD_FRAGS(nab, nbb, 0, 0);
            ab = nab; bb = nbb; e_st = c_st;
            if (++c_st == STAGES) { c_st = 0; c_ph ^= 1; }
        }
        MMA_BLOCK(1);
    }

    // ---- epilogue: f32 (exact integer) * row_scale, float2 stores ----
    const int mbase = m_tile * BM + wm * 32;
    const int nbase = n_tile * BN + wn * 64 + (lane & 3) * 2;
#pragma unroll
    for (int mt = 0; mt < 2; ++mt) {
        const int r0 = mbase + mt * 16 + (lane >> 2);
        const float s0 = g_row_scale[r0];
        const float s1 = g_row_scale[r0 + 8];
        float* o0 = out + (size_t)r0 * N_DIM + nbase;
        float* o1 = o0 + (size_t)8 * N_DIM;
#pragma unroll
        for (int nt = 0; nt < 8; ++nt) {
            float2 v0, v1;
            v0.x = acc[mt][nt][0] * s0;
            v0.y = acc[mt][nt][1] * s0;
            v1.x = acc[mt][nt][2] * s1;
            v1.y = acc[mt][nt][3] * s1;
            *(float2*)(o0 + nt * 8) = v0;
            *(float2*)(o1 + nt * 8) = v1;
        }
    }
#undef PRODUCE
#undef LOAD_FRAGS
#undef MMA_BLOCK
#undef FULL_BAR
#undef EMPTY_BAR
}

// ---------------------------------------------------------------------------
// Host launcher — 3 launches: wabs=0, quant_fused=1, gemm=2
// ---------------------------------------------------------------------------
extern "C" void kernel_launch(void* const* d_in, const int* in_sizes, int n_in,
                              void* d_out, int out_size) {
    const float* x = (const float*)d_in[0];
    const float* w = (const float*)d_in[1];
    if (n_in >= 2 && in_sizes[0] == W_ELEMS && in_sizes[1] == X_ELEMS) {
        const float* t = x; x = w; w = t;   // defensive: swapped metadata order
    }
    float* out = (float*)d_out;

    void* p_qw = nullptr;
    void* p_qx = nullptr;
    cudaGetSymbolAddress(&p_qw, g_qw);
    cudaGetSymbolAddress(&p_qx, g_qx);

    cudaFuncSetAttribute(gemm_bf16, cudaFuncAttributeMaxDynamicSharedMemorySize, SMEM_BYTES);

    wabs_partial_kernel<<<1024, 256>>>((const float4*)w, W_ELEMS / 4);
    quant_fused_kernel<<<QW_BLOCKS + M_DIM, 256>>>((const float4*)w, x, W_ELEMS / 4);

    gemm_bf16<<<M_TILES * N_TILES, 256, SMEM_BYTES>>>(
        (const __nv_bfloat16*)p_qx, (const __nv_bfloat16*)p_qw, out);
}

// round 13
// speedup vs baseline: 1.2300x; 1.2300x over previous
#include <cuda_runtime.h>
#include <cuda_bf16.h>
#include <cstdint>

// ---------------------------------------------------------------------------
// Problem geometry
// ---------------------------------------------------------------------------
#define M_DIM 16384              // 4 * 4096 rows of x
#define K_DIM 4096
#define N_DIM 11008
#define W_ELEMS (N_DIM * K_DIM)  // 45088768
#define X_ELEMS (M_DIM * K_DIM)  // 67108864

// GEMM tiling (bf16): CTA 128x128, warp tile 32x64, BK=64
#define BM 128
#define BN 128
#define BK 64
#define NUM_KITER (K_DIM / BK)     // 64
#define N_TILES (N_DIM / BN)       // 86
#define M_TILES (M_DIM / BM)       // 128
#define GROUP_M 8

#define ROW_BYTES 128                           // BK * 2 (bf16)
#define ROW_PAD 144                             // 128B data + 16B pad (conflict-free)
#define A_STAGE_BYTES (BM * ROW_PAD)            // 18432
#define B_STAGE_BYTES (BN * ROW_PAD)            // 18432
#define STAGE_BYTES (A_STAGE_BYTES + B_STAGE_BYTES)
#define STAGES 3
#define MBAR_BYTES 64
#define SMEM_BYTES (STAGES * STAGE_BYTES + MBAR_BYTES)  // 110656 (2 CTAs/SM)

#define QW_BLOCKS 4096

// ---------------------------------------------------------------------------
// Device scratch (allocation-free rule: __device__ globals)
// ---------------------------------------------------------------------------
__device__ __align__(1024) __nv_bfloat16 g_qw[W_ELEMS];  // ternary {-1,0,1}
__device__ __align__(1024) __nv_bfloat16 g_qx[X_ELEMS];  // integers [-128,127]
__device__ float g_row_scale[M_DIM];                     // gamma_x[m]*gamma_w/127
__device__ float g_partial[1024];

// ---------------------------------------------------------------------------
// PTX helpers (sm_80-class baseline; no 'a' features)
// ---------------------------------------------------------------------------
#define CP_ASYNC16(smem_u32, gptr) \
    asm volatile("cp.async.cg.shared.global.L2::128B [%0], [%1], 16;" \
                 :: "r"(smem_u32), "l"(gptr) : "memory")

#define CP_ASYNC_MBAR_ARRIVE(mbar) \
    asm volatile("cp.async.mbarrier.arrive.noinc.shared.b64 [%0];" \
                 :: "r"((uint32_t)(mbar)) : "memory")

#define MBARRIER_INIT(mbar, count) \
    asm volatile("mbarrier.init.shared.b64 [%0], %1;" \
                 :: "r"((uint32_t)(mbar)), "r"((uint32_t)(count)) : "memory")

#define MBARRIER_ARRIVE(mbar) \
    asm volatile("mbarrier.arrive.shared.b64 _, [%0];" \
                 :: "r"((uint32_t)(mbar)) : "memory")

#define MBARRIER_WAIT_PARITY(mbar_smem_addr, phase_parity) do {                       \
    uint32_t _mbar = (uint32_t)(mbar_smem_addr);                                      \
    uint32_t _parity = (uint32_t)(phase_parity);                                      \
    uint32_t _done;                                                                   \
    asm volatile(                                                                     \
        "{\n\t"                                                                       \
        ".reg .pred p;\n\t"                                                           \
        "mbarrier.try_wait.parity.acquire.cta.shared::cta.b64 p, [%1], %2;\n\t"       \
        "selp.b32 %0, 1, 0, p;\n\t"                                                   \
        "}"                                                                           \
        : "=r"(_done) : "r"(_mbar), "r"(_parity) : "memory");                         \
    if (!_done) {                                                                     \
        asm volatile(                                                                 \
            "{\n\t"                                                                   \
            ".reg .pred P1;\n\t"                                                      \
            "WAIT_LOOP_%=:\n\t"                                                       \
            "mbarrier.try_wait.parity.acquire.cta.shared::cta.b64 P1, [%0], %1, 0x989680;\n\t" \
            "@P1 bra.uni WAIT_DONE_%=;\n\t"                                           \
            "bra.uni WAIT_LOOP_%=;\n\t"                                               \
            "WAIT_DONE_%=:\n\t"                                                       \
            "}"                                                                       \
            :: "r"(_mbar), "r"(_parity) : "memory");                                  \
    }                                                                                 \
} while (0)

#define LDM_X4(r, addr) \
    asm volatile("ldmatrix.sync.aligned.m8n8.x4.shared.b16 {%0,%1,%2,%3}, [%4];" \
                 : "=r"((r)[0]), "=r"((r)[1]), "=r"((r)[2]), "=r"((r)[3]) \
                 : "r"(addr))

#define MMA_BF16(d, a, b0, b1) \
    asm volatile("mma.sync.aligned.m16n8k16.row.col.f32.bf16.bf16.f32 " \
                 "{%0,%1,%2,%3}, {%4,%5,%6,%7}, {%8,%9}, {%0,%1,%2,%3};" \
                 : "+f"((d)[0]), "+f"((d)[1]), "+f"((d)[2]), "+f"((d)[3]) \
                 : "r"((a)[0]), "r"((a)[1]), "r"((a)[2]), "r"((a)[3]), \
                   "r"(b0), "r"(b1))

// ---------------------------------------------------------------------------
// In-block gamma_w reconstruction (deterministic tree, bit-identical always)
// ---------------------------------------------------------------------------
__device__ __forceinline__ float reduce_gamma(float* sdata) {
    const int t = threadIdx.x;
    float s = g_partial[t] + g_partial[t + 256] + g_partial[t + 512] + g_partial[t + 768];
    sdata[t] = s;
    __syncthreads();
    for (int off = 128; off > 0; off >>= 1) {
        if (t < off) sdata[t] += sdata[t + off];
        __syncthreads();
    }
    float g = sdata[0] / (float)W_ELEMS + 1e-5f;
    __syncthreads();
    return g;
}

// ---------------------------------------------------------------------------
// Kernel 0: per-block partial sums of |W|  (exactly 1024 blocks)
// ---------------------------------------------------------------------------
__global__ void wabs_partial_kernel(const float4* __restrict__ w, int n4) {
    __shared__ float sdata[256];
    float s = 0.f;
    for (int i = blockIdx.x * blockDim.x + threadIdx.x; i < n4; i += gridDim.x * blockDim.x) {
        float4 v = w[i];
        s += fabsf(v.x) + fabsf(v.y) + fabsf(v.z) + fabsf(v.w);
    }
    sdata[threadIdx.x] = s;
    __syncthreads();
    for (int off = 128; off > 0; off >>= 1) {
        if (threadIdx.x < off) sdata[threadIdx.x] += sdata[threadIdx.x + off];
        __syncthreads();
    }
    if (threadIdx.x == 0) g_partial[blockIdx.x] = sdata[0];
}

// ---------------------------------------------------------------------------
// Kernel 1 (fused): blocks [0, QW_BLOCKS) quantize W (ternary bf16);
//                   blocks [QW_BLOCKS, QW_BLOCKS+M_DIM) quantize one x row.
// ---------------------------------------------------------------------------
__global__ void quant_fused_kernel(const float4* __restrict__ w,
                                   const float* __restrict__ x, int w_n4) {
    __shared__ float sdata[256];
    const float gw = reduce_gamma(sdata);
    const int t = threadIdx.x;

    if (blockIdx.x < QW_BLOCKS) {
        __nv_bfloat162* qw2 = (__nv_bfloat162*)g_qw;
        for (int i = blockIdx.x * 256 + t; i < w_n4; i += QW_BLOCKS * 256) {
            float4 v = w[i];
            float q0 = fminf(fmaxf(rintf(v.x / gw), -1.f), 1.f);
            float q1 = fminf(fmaxf(rintf(v.y / gw), -1.f), 1.f);
            float q2 = fminf(fmaxf(rintf(v.z / gw), -1.f), 1.f);
            float q3 = fminf(fmaxf(rintf(v.w / gw), -1.f), 1.f);
            qw2[i * 2]     = __floats2bfloat162_rn(q0, q1);
            qw2[i * 2 + 1] = __floats2bfloat162_rn(q2, q3);
        }
        return;
    }

    const int row = blockIdx.x - QW_BLOCKS;
    const float4* xr = (const float4*)(x + (size_t)row * K_DIM);

    float4 vv[4];
    float m = 0.f;
#pragma unroll
    for (int j = 0; j < 4; ++j) {
        float4 v = xr[t + j * 256];
        vv[j] = v;
        m = fmaxf(m, fmaxf(fmaxf(fabsf(v.x), fabsf(v.y)), fmaxf(fabsf(v.z), fabsf(v.w))));
    }
    sdata[t] = m;
    __syncthreads();
    for (int off = 128; off > 0; off >>= 1) {
        if (t < off) sdata[t] = fmaxf(sdata[t], sdata[t + off]);
        __syncthreads();
    }
    const float gx = sdata[0] + 1e-5f;

    __nv_bfloat162* qr = (__nv_bfloat162*)(g_qx + (size_t)row * K_DIM);
#pragma unroll
    for (int j = 0; j < 4; ++j) {
        float4 v = vv[j];
        float q0 = fminf(fmaxf(rintf((127.f * v.x) / gx), -128.f), 127.f);
        float q1 = fminf(fmaxf(rintf((127.f * v.y) / gx), -128.f), 127.f);
        float q2 = fminf(fmaxf(rintf((127.f * v.z) / gx), -128.f), 127.f);
        float q3 = fminf(fmaxf(rintf((127.f * v.w) / gx), -128.f), 127.f);
        int i = t + j * 256;
        qr[i * 2]     = __floats2bfloat162_rn(q0, q1);
        qr[i * 2 + 1] = __floats2bfloat162_rn(q2, q3);
    }
    if (t == 0) g_row_scale[row] = gx * gw * (1.0f / 127.0f);
}

// ---------------------------------------------------------------------------
// Kernel 2: bf16 GEMM via mma.m16n8k16 (integer-exact). R11 structure with
// two isolated deltas:
//   (1) PRODUCE(kk+2) moved mid-iteration (after ks=1) so its EMPTY wait on
//       "all warps done stage kk-1" no longer blocks the start of compute kk.
//   (2) EMPTY arrivals elected (count 8, lane 0 per warp), placed right after
//       the last LDSM of the stage (early release).
//   CTA 128x128, 8 warps (4m x 2n), warp tile 32x64, BK=64, 3 stages, 2 CTA/SM.
//   out[m, n] = (sum_k A[m,k]*B[n,k]) * g_row_scale[m]
// ---------------------------------------------------------------------------
__global__ void __launch_bounds__(256, 2)
gemm_bf16(const __nv_bfloat16* __restrict__ A, const __nv_bfloat16* __restrict__ B,
          float* __restrict__ out) {
    extern __shared__ char smem[];
    const uint32_t sb = (uint32_t)__cvta_generic_to_shared(smem);
    const int tid = threadIdx.x;
    const int wid = tid >> 5;
    const int lane = tid & 31;
    const int wm = wid >> 1;   // 0..3 (m)
    const int wn = wid & 1;    // 0..1 (n)

    const uint32_t mb = sb + STAGES * STAGE_BYTES;
#define FULL_BAR(s)  (mb + (uint32_t)(s) * 16u)
#define EMPTY_BAR(s) (mb + (uint32_t)(s) * 16u + 8u)

    if (tid == 0) {
#pragma unroll
        for (int s = 0; s < STAGES; ++s) {
            MBARRIER_INIT(FULL_BAR(s), 256);   // one async arrive per thread
            MBARRIER_INIT(EMPTY_BAR(s), 8);    // one arrive per WARP (lane 0)
        }
    }
    __syncthreads();   // barriers visible before any use (only block sync here)

    // tile mapping with GROUP_M swizzle for L2 reuse
    const int per_group = GROUP_M * N_TILES;
    const int group = blockIdx.x / per_group;
    const int rem = blockIdx.x - group * per_group;
    const int m_tile = group * GROUP_M + (rem % GROUP_M);
    const int n_tile = rem / GROUP_M;

    const char* gA = (const char*)(A + (size_t)(m_tile * BM) * K_DIM);
    const char* gB = (const char*)(B + (size_t)(n_tile * BN) * K_DIM);
    const size_t KROW = (size_t)K_DIM * 2;   // bytes per global row

    const int lrw = tid >> 3;        // base row 0..31
    const int lcc = tid & 7;         // 16B chunk within 128B row

    int p_st = 0, p_ph = 1;          // producer cursor (empty-wait), phase 1

#define PRODUCE(kt) do {                                                            \
    MBARRIER_WAIT_PARITY(EMPTY_BAR(p_st), p_ph);                                    \
    uint32_t abase = sb + (uint32_t)p_st * STAGE_BYTES + lcc * 16;                  \
    uint32_t bbase = abase + A_STAGE_BYTES;                                         \
    const char* ga = gA + (size_t)(kt) * ROW_BYTES + lcc * 16;                      \
    const char* gb = gB + (size_t)(kt) * ROW_BYTES + lcc * 16;                      \
    _Pragma("unroll")                                                               \
    for (int t = 0; t < 4; ++t) {                                                   \
        int row = lrw + t * 32;                                                     \
        CP_ASYNC16(abase + row * ROW_PAD, ga + (size_t)row * KROW);                 \
        CP_ASYNC16(bbase + row * ROW_PAD, gb + (size_t)row * KROW);                 \
    }                                                                               \
    CP_ASYNC_MBAR_ARRIVE(FULL_BAR(p_st));                                           \
    if (++p_st == STAGES) { p_st = 0; p_ph ^= 1; }                                  \
} while (0)

    float acc[2][8][4];
#pragma unroll
    for (int mt = 0; mt < 2; ++mt)
#pragma unroll
        for (int nt = 0; nt < 8; ++nt)
#pragma unroll
            for (int j = 0; j < 4; ++j) acc[mt][nt][j] = 0.f;

    const int lrow = lane & 15;
    const uint32_t lhalf = (uint32_t)(lane >> 4) * 16;
    const uint32_t a_row_off = (uint32_t)(wm * 32 + lrow) * ROW_PAD + lhalf;
    const uint32_t b_row_off = (uint32_t)(wn * 64 + lrow) * ROW_PAD + lhalf;

    uint32_t afr[2][2][4];   // [buf][mt][4]
    uint32_t bfr[2][4][4];   // [buf][np][4]

#define LOAD_FRAGS(base_a, base_b, ks, fb) do {                                     \
    const uint32_t kbyte = (uint32_t)(ks) * 32;                                     \
    _Pragma("unroll")                                                               \
    for (int mt = 0; mt < 2; ++mt)                                                  \
        LDM_X4(afr[fb][mt], (base_a) + a_row_off + (uint32_t)(mt * 16) * ROW_PAD + kbyte); \
    _Pragma("unroll")                                                               \
    for (int np = 0; np < 4; ++np)                                                  \
        LDM_X4(bfr[fb][np], (base_b) + b_row_off + (uint32_t)(np * 16) * ROW_PAD + kbyte); \
} while (0)

#define MMA_BLOCK(fb) do {                                                          \
    _Pragma("unroll")                                                               \
    for (int mt = 0; mt < 2; ++mt)                                                  \
        _Pragma("unroll")                                                           \
        for (int nt = 0; nt < 8; ++nt) {                                            \
            const int np = nt >> 1, sel = nt & 1;                                   \
            MMA_BF16(acc[mt][nt], afr[fb][mt], bfr[fb][np][sel], bfr[fb][np][2 + sel]); \
        }                                                                           \
} while (0)

    // prologue: fill stages 0,1 (empty waits pass immediately at phase 1)
    PRODUCE(0);
    PRODUCE(1);

    int c_st = 0, c_ph = 0;   // consumer cursor

    for (int kk = 0; kk < NUM_KITER; ++kk) {
        MBARRIER_WAIT_PARITY(FULL_BAR(c_st), c_ph);   // stage kk resident

        const uint32_t ab = sb + (uint32_t)c_st * STAGE_BYTES;
        const uint32_t bb = ab + A_STAGE_BYTES;

        LOAD_FRAGS(ab, bb, 0, 0);   // prime frag pipeline for this iter

        // ks = 0
        LOAD_FRAGS(ab, bb, 1, 1);
        MMA_BLOCK(0);
        // ks = 1
        LOAD_FRAGS(ab, bb, 2, 0);
        MMA_BLOCK(1);

        // mid-iteration produce: EMPTY wait on stage kk-1 is ~always satisfied
        // here (this warp is >half done with kk), prefetch still ~1.5 iters deep
        if (kk + 2 < NUM_KITER) PRODUCE(kk + 2);

        // ks = 2 (contains the LAST smem reads of this stage: ks=3 frags)
        LOAD_FRAGS(ab, bb, 3, 1);
        if (lane == 0) MBARRIER_ARRIVE(EMPTY_BAR(c_st));   // early elected release
        MMA_BLOCK(0);
        // ks = 3 (registers only)
        MMA_BLOCK(1);

        if (++c_st == STAGES) { c_st = 0; c_ph ^= 1; }
    }

    // ---- epilogue: f32 (exact integer) * row_scale, float2 stores ----
    const int mbase = m_tile * BM + wm * 32;
    const int nbase = n_tile * BN + wn * 64 + (lane & 3) * 2;
#pragma unroll
    for (int mt = 0; mt < 2; ++mt) {
        const int r0 = mbase + mt * 16 + (lane >> 2);
        const float s0 = g_row_scale[r0];
        const float s1 = g_row_scale[r0 + 8];
        float* o0 = out + (size_t)r0 * N_DIM + nbase;
        float* o1 = o0 + (size_t)8 * N_DIM;
#pragma unroll
        for (int nt = 0; nt < 8; ++nt) {
            float2 v0, v1;
            v0.x = acc[mt][nt][0] * s0;
            v0.y = acc[mt][nt][1] * s0;
            v1.x = acc[mt][nt][2] * s1;
            v1.y = acc[mt][nt][3] * s1;
            *(float2*)(o0 + nt * 8) = v0;
            *(float2*)(o1 + nt * 8) = v1;
        }
    }
#undef PRODUCE
#undef LOAD_FRAGS
#undef MMA_BLOCK
#undef FULL_BAR
#undef EMPTY_BAR
}

// ---------------------------------------------------------------------------
// Host launcher — 3 launches: wabs=0, quant_fused=1, gemm=2
// ---------------------------------------------------------------------------
extern "C" void kernel_launch(void* const* d_in, const int* in_sizes, int n_in,
                              void* d_out, int out_size) {
    const float* x = (const float*)d_in[0];
    const float* w = (const float*)d_in[1];
    if (n_in >= 2 && in_sizes[0] == W_ELEMS && in_sizes[1] == X_ELEMS) {
        const float* t = x; x = w; w = t;   // defensive: swapped metadata order
    }
    float* out = (float*)d_out;

    void* p_qw = nullptr;
    void* p_qx = nullptr;
    cudaGetSymbolAddress(&p_qw, g_qw);
    cudaGetSymbolAddress(&p_qx, g_qx);

    cudaFuncSetAttribute(gemm_bf16, cudaFuncAttributeMaxDynamicSharedMemorySize, SMEM_BYTES);

    wabs_partial_kernel<<<1024, 256>>>((const float4*)w, W_ELEMS / 4);
    quant_fused_kernel<<<QW_BLOCKS + M_DIM, 256>>>((const float4*)w, x, W_ELEMS / 4);

    gemm_bf16<<<M_TILES * N_TILES, 256, SMEM_BYTES>>>(
        (const __nv_bfloat16*)p_qx, (const __nv_bfloat16*)p_qw, out);
}

// round 14
// speedup vs baseline: 1.2320x; 1.0016x over previous
#include <cuda_runtime.h>
#include <cuda_bf16.h>
#include <cstdint>

// ---------------------------------------------------------------------------
// Problem geometry
// ---------------------------------------------------------------------------
#define M_DIM 16384              // 4 * 4096 rows of x
#define K_DIM 4096
#define N_DIM 11008
#define W_ELEMS (N_DIM * K_DIM)  // 45088768
#define X_ELEMS (M_DIM * K_DIM)  // 67108864

// GEMM tiling (bf16): CTA 128x128, warp tile 32x64, BK=64
#define BM 128
#define BN 128
#define BK 64
#define NUM_KITER (K_DIM / BK)     // 64
#define N_TILES (N_DIM / BN)       // 86
#define M_TILES (M_DIM / BM)       // 128
#define GROUP_M 8

#define ROW_BYTES 128                           // BK * 2 (bf16)
#define ROW_PAD 144                             // 128B data + 16B pad (conflict-free)
#define A_STAGE_BYTES (BM * ROW_PAD)            // 18432
#define B_STAGE_BYTES (BN * ROW_PAD)            // 18432
#define STAGE_BYTES (A_STAGE_BYTES + B_STAGE_BYTES)
#define STAGES 3
#define MBAR_BYTES 64
#define SMEM_BYTES (STAGES * STAGE_BYTES + MBAR_BYTES)  // 110656 (2 CTAs/SM)

#define QW_BLOCKS 4096

// ---------------------------------------------------------------------------
// Device scratch (allocation-free rule: __device__ globals)
// ---------------------------------------------------------------------------
__device__ __align__(1024) __nv_bfloat16 g_qw[W_ELEMS];  // ternary {-1,0,1}
__device__ __align__(1024) __nv_bfloat16 g_qx[X_ELEMS];  // integers [-128,127]
__device__ float g_row_scale[M_DIM];                     // gamma_x[m]*gamma_w/127
__device__ float g_partial[1024];

// ---------------------------------------------------------------------------
// PTX helpers (sm_80-class baseline; no 'a' features)
// ---------------------------------------------------------------------------
#define CP_ASYNC16(smem_u32, gptr) \
    asm volatile("cp.async.cg.shared.global.L2::128B [%0], [%1], 16;" \
                 :: "r"(smem_u32), "l"(gptr) : "memory")

#define CP_ASYNC_MBAR_ARRIVE(mbar) \
    asm volatile("cp.async.mbarrier.arrive.noinc.shared.b64 [%0];" \
                 :: "r"((uint32_t)(mbar)) : "memory")

#define MBARRIER_INIT(mbar, count) \
    asm volatile("mbarrier.init.shared.b64 [%0], %1;" \
                 :: "r"((uint32_t)(mbar)), "r"((uint32_t)(count)) : "memory")

#define MBARRIER_ARRIVE(mbar) \
    asm volatile("mbarrier.arrive.shared.b64 _, [%0];" \
                 :: "r"((uint32_t)(mbar)) : "memory")

#define MBARRIER_WAIT_PARITY(mbar_smem_addr, phase_parity) do {                       \
    uint32_t _mbar = (uint32_t)(mbar_smem_addr);                                      \
    uint32_t _parity = (uint32_t)(phase_parity);                                      \
    uint32_t _done;                                                                   \
    asm volatile(                                                                     \
        "{\n\t"                                                                       \
        ".reg .pred p;\n\t"                                                           \
        "mbarrier.try_wait.parity.acquire.cta.shared::cta.b64 p, [%1], %2;\n\t"       \
        "selp.b32 %0, 1, 0, p;\n\t"                                                   \
        "}"                                                                           \
        : "=r"(_done) : "r"(_mbar), "r"(_parity) : "memory");                         \
    if (!_done) {                                                                     \
        asm volatile(                                                                 \
            "{\n\t"                                                                   \
            ".reg .pred P1;\n\t"                                                      \
            "WAIT_LOOP_%=:\n\t"                                                       \
            "mbarrier.try_wait.parity.acquire.cta.shared::cta.b64 P1, [%0], %1, 0x989680;\n\t" \
            "@P1 bra.uni WAIT_DONE_%=;\n\t"                                           \
            "bra.uni WAIT_LOOP_%=;\n\t"                                               \
            "WAIT_DONE_%=:\n\t"                                                       \
            "}"                                                                       \
            :: "r"(_mbar), "r"(_parity) : "memory");                                  \
    }                                                                                 \
} while (0)

#define LDM_X4(r, addr) \
    asm volatile("ldmatrix.sync.aligned.m8n8.x4.shared.b16 {%0,%1,%2,%3}, [%4];" \
                 : "=r"((r)[0]), "=r"((r)[1]), "=r"((r)[2]), "=r"((r)[3]) \
                 : "r"(addr))

#define MMA_BF16(d, a, b0, b1) \
    asm volatile("mma.sync.aligned.m16n8k16.row.col.f32.bf16.bf16.f32 " \
                 "{%0,%1,%2,%3}, {%4,%5,%6,%7}, {%8,%9}, {%0,%1,%2,%3};" \
                 : "+f"((d)[0]), "+f"((d)[1]), "+f"((d)[2]), "+f"((d)[3]) \
                 : "r"((a)[0]), "r"((a)[1]), "r"((a)[2]), "r"((a)[3]), \
                   "r"(b0), "r"(b1))

// ---------------------------------------------------------------------------
// In-block gamma_w reconstruction (deterministic tree, bit-identical always)
// ---------------------------------------------------------------------------
__device__ __forceinline__ float reduce_gamma(float* sdata) {
    const int t = threadIdx.x;
    float s = g_partial[t] + g_partial[t + 256] + g_partial[t + 512] + g_partial[t + 768];
    sdata[t] = s;
    __syncthreads();
    for (int off = 128; off > 0; off >>= 1) {
        if (t < off) sdata[t] += sdata[t + off];
        __syncthreads();
    }
    float g = sdata[0] / (float)W_ELEMS + 1e-5f;
    __syncthreads();
    return g;
}

// ---------------------------------------------------------------------------
// Kernel 0: per-block partial sums of |W|  (exactly 1024 blocks)
// ---------------------------------------------------------------------------
__global__ void wabs_partial_kernel(const float4* __restrict__ w, int n4) {
    __shared__ float sdata[256];
    float s = 0.f;
    for (int i = blockIdx.x * blockDim.x + threadIdx.x; i < n4; i += gridDim.x * blockDim.x) {
        float4 v = w[i];
        s += fabsf(v.x) + fabsf(v.y) + fabsf(v.z) + fabsf(v.w);
    }
    sdata[threadIdx.x] = s;
    __syncthreads();
    for (int off = 128; off > 0; off >>= 1) {
        if (threadIdx.x < off) sdata[threadIdx.x] += sdata[threadIdx.x + off];
        __syncthreads();
    }
    if (threadIdx.x == 0) g_partial[blockIdx.x] = sdata[0];
}

// ---------------------------------------------------------------------------
// Kernel 1 (fused): blocks [0, QW_BLOCKS) quantize W (ternary bf16);
//                   blocks [QW_BLOCKS, QW_BLOCKS+M_DIM) quantize one x row.
// ---------------------------------------------------------------------------
__global__ void quant_fused_kernel(const float4* __restrict__ w,
                                   const float* __restrict__ x, int w_n4) {
    __shared__ float sdata[256];
    const float gw = reduce_gamma(sdata);
    const int t = threadIdx.x;

    if (blockIdx.x < QW_BLOCKS) {
        __nv_bfloat162* qw2 = (__nv_bfloat162*)g_qw;
        for (int i = blockIdx.x * 256 + t; i < w_n4; i += QW_BLOCKS * 256) {
            float4 v = w[i];
            float q0 = fminf(fmaxf(rintf(v.x / gw), -1.f), 1.f);
            float q1 = fminf(fmaxf(rintf(v.y / gw), -1.f), 1.f);
            float q2 = fminf(fmaxf(rintf(v.z / gw), -1.f), 1.f);
            float q3 = fminf(fmaxf(rintf(v.w / gw), -1.f), 1.f);
            qw2[i * 2]     = __floats2bfloat162_rn(q0, q1);
            qw2[i * 2 + 1] = __floats2bfloat162_rn(q2, q3);
        }
        return;
    }

    const int row = blockIdx.x - QW_BLOCKS;
    const float4* xr = (const float4*)(x + (size_t)row * K_DIM);

    float4 vv[4];
    float m = 0.f;
#pragma unroll
    for (int j = 0; j < 4; ++j) {
        float4 v = xr[t + j * 256];
        vv[j] = v;
        m = fmaxf(m, fmaxf(fmaxf(fabsf(v.x), fabsf(v.y)), fmaxf(fabsf(v.z), fabsf(v.w))));
    }
    sdata[t] = m;
    __syncthreads();
    for (int off = 128; off > 0; off >>= 1) {
        if (t < off) sdata[t] = fmaxf(sdata[t], sdata[t + off]);
        __syncthreads();
    }
    const float gx = sdata[0] + 1e-5f;

    __nv_bfloat162* qr = (__nv_bfloat162*)(g_qx + (size_t)row * K_DIM);
#pragma unroll
    for (int j = 0; j < 4; ++j) {
        float4 v = vv[j];
        float q0 = fminf(fmaxf(rintf((127.f * v.x) / gx), -128.f), 127.f);
        float q1 = fminf(fmaxf(rintf((127.f * v.y) / gx), -128.f), 127.f);
        float q2 = fminf(fmaxf(rintf((127.f * v.z) / gx), -128.f), 127.f);
        float q3 = fminf(fmaxf(rintf((127.f * v.w) / gx), -128.f), 127.f);
        int i = t + j * 256;
        qr[i * 2]     = __floats2bfloat162_rn(q0, q1);
        qr[i * 2 + 1] = __floats2bfloat162_rn(q2, q3);
    }
    if (t == 0) g_row_scale[row] = gx * gw * (1.0f / 127.0f);
}

// ---------------------------------------------------------------------------
// Kernel 2: bf16 GEMM via mma.m16n8k16 (integer-exact). R13 champion with ONE
// delta: the mid-iteration PRODUCE is split into an A-half (after ks=0 MMAs)
// and a B-half (after ks=1 MMAs) to halve the instantaneous cp.async burst
// competing with LDSM on the LSU path. The single cp.async.mbarrier.arrive
// after the B-half covers both halves (fires when ALL prior cp.asyncs of the
// thread complete), so barrier counts are unchanged.
//   CTA 128x128, 8 warps (4m x 2n), warp tile 32x64, BK=64, 3 stages, 2 CTA/SM.
//   out[m, n] = (sum_k A[m,k]*B[n,k]) * g_row_scale[m]
// ---------------------------------------------------------------------------
__global__ void __launch_bounds__(256, 2)
gemm_bf16(const __nv_bfloat16* __restrict__ A, const __nv_bfloat16* __restrict__ B,
          float* __restrict__ out) {
    extern __shared__ char smem[];
    const uint32_t sb = (uint32_t)__cvta_generic_to_shared(smem);
    const int tid = threadIdx.x;
    const int wid = tid >> 5;
    const int lane = tid & 31;
    const int wm = wid >> 1;   // 0..3 (m)
    const int wn = wid & 1;    // 0..1 (n)

    const uint32_t mb = sb + STAGES * STAGE_BYTES;
#define FULL_BAR(s)  (mb + (uint32_t)(s) * 16u)
#define EMPTY_BAR(s) (mb + (uint32_t)(s) * 16u + 8u)

    if (tid == 0) {
#pragma unroll
        for (int s = 0; s < STAGES; ++s) {
            MBARRIER_INIT(FULL_BAR(s), 256);   // one async arrive per thread
            MBARRIER_INIT(EMPTY_BAR(s), 8);    // one arrive per WARP (lane 0)
        }
    }
    __syncthreads();   // barriers visible before any use (only block sync here)

    // tile mapping with GROUP_M swizzle for L2 reuse
    const int per_group = GROUP_M * N_TILES;
    const int group = blockIdx.x / per_group;
    const int rem = blockIdx.x - group * per_group;
    const int m_tile = group * GROUP_M + (rem % GROUP_M);
    const int n_tile = rem / GROUP_M;

    const char* gA = (const char*)(A + (size_t)(m_tile * BM) * K_DIM);
    const char* gB = (const char*)(B + (size_t)(n_tile * BN) * K_DIM);
    const size_t KROW = (size_t)K_DIM * 2;   // bytes per global row

    const int lrw = tid >> 3;        // base row 0..31
    const int lcc = tid & 7;         // 16B chunk within 128B row

    int p_st = 0, p_ph = 1;          // producer cursor (empty-wait), phase 1

    // A-half: EMPTY wait + A tile loads (4 cp.async per thread)
#define PRODUCE_A(kt) do {                                                          \
    MBARRIER_WAIT_PARITY(EMPTY_BAR(p_st), p_ph);                                    \
    uint32_t abase = sb + (uint32_t)p_st * STAGE_BYTES + lcc * 16;                  \
    const char* ga = gA + (size_t)(kt) * ROW_BYTES + lcc * 16;                      \
    _Pragma("unroll")                                                               \
    for (int t = 0; t < 4; ++t) {                                                   \
        int row = lrw + t * 32;                                                     \
        CP_ASYNC16(abase + row * ROW_PAD, ga + (size_t)row * KROW);                 \
    }                                                                               \
} while (0)

    // B-half: B tile loads + single arrive covering both halves; cursor bump
#define PRODUCE_B(kt) do {                                                          \
    uint32_t bbase = sb + (uint32_t)p_st * STAGE_BYTES + A_STAGE_BYTES + lcc * 16;  \
    const char* gb = gB + (size_t)(kt) * ROW_BYTES + lcc * 16;                      \
    _Pragma("unroll")                                                               \
    for (int t = 0; t < 4; ++t) {                                                   \
        int row = lrw + t * 32;                                                     \
        CP_ASYNC16(bbase + row * ROW_PAD, gb + (size_t)row * KROW);                 \
    }                                                                               \
    CP_ASYNC_MBAR_ARRIVE(FULL_BAR(p_st));                                           \
    if (++p_st == STAGES) { p_st = 0; p_ph ^= 1; }                                  \
} while (0)

    float acc[2][8][4];
#pragma unroll
    for (int mt = 0; mt < 2; ++mt)
#pragma unroll
        for (int nt = 0; nt < 8; ++nt)
#pragma unroll
            for (int j = 0; j < 4; ++j) acc[mt][nt][j] = 0.f;

    const int lrow = lane & 15;
    const uint32_t lhalf = (uint32_t)(lane >> 4) * 16;
    const uint32_t a_row_off = (uint32_t)(wm * 32 + lrow) * ROW_PAD + lhalf;
    const uint32_t b_row_off = (uint32_t)(wn * 64 + lrow) * ROW_PAD + lhalf;

    uint32_t afr[2][2][4];   // [buf][mt][4]
    uint32_t bfr[2][4][4];   // [buf][np][4]

#define LOAD_FRAGS(base_a, base_b, ks, fb) do {                                     \
    const uint32_t kbyte = (uint32_t)(ks) * 32;                                     \
    _Pragma("unroll")                                                               \
    for (int mt = 0; mt < 2; ++mt)                                                  \
        LDM_X4(afr[fb][mt], (base_a) + a_row_off + (uint32_t)(mt * 16) * ROW_PAD + kbyte); \
    _Pragma("unroll")                                                               \
    for (int np = 0; np < 4; ++np)                                                  \
        LDM_X4(bfr[fb][np], (base_b) + b_row_off + (uint32_t)(np * 16) * ROW_PAD + kbyte); \
} while (0)

#define MMA_BLOCK(fb) do {                                                          \
    _Pragma("unroll")                                                               \
    for (int mt = 0; mt < 2; ++mt)                                                  \
        _Pragma("unroll")                                                           \
        for (int nt = 0; nt < 8; ++nt) {                                            \
            const int np = nt >> 1, sel = nt & 1;                                   \
            MMA_BF16(acc[mt][nt], afr[fb][mt], bfr[fb][np][sel], bfr[fb][np][2 + sel]); \
        }                                                                           \
} while (0)

    // prologue: fill stages 0,1 (empty waits pass immediately at phase 1)
    PRODUCE_A(0); PRODUCE_B(0);
    PRODUCE_A(1); PRODUCE_B(1);

    int c_st = 0, c_ph = 0;   // consumer cursor

    for (int kk = 0; kk < NUM_KITER; ++kk) {
        MBARRIER_WAIT_PARITY(FULL_BAR(c_st), c_ph);   // stage kk resident

        const uint32_t ab = sb + (uint32_t)c_st * STAGE_BYTES;
        const uint32_t bb = ab + A_STAGE_BYTES;

        LOAD_FRAGS(ab, bb, 0, 0);   // prime frag pipeline for this iter

        // ks = 0
        LOAD_FRAGS(ab, bb, 1, 1);
        MMA_BLOCK(0);

        // producer A-half (EMPTY wait ~always satisfied here)
        if (kk + 2 < NUM_KITER) PRODUCE_A(kk + 2);

        // ks = 1
        LOAD_FRAGS(ab, bb, 2, 0);
        MMA_BLOCK(1);

        // producer B-half + arrive
        if (kk + 2 < NUM_KITER) PRODUCE_B(kk + 2);

        // ks = 2 (contains the LAST smem reads of this stage: ks=3 frags)
        LOAD_FRAGS(ab, bb, 3, 1);
        if (lane == 0) MBARRIER_ARRIVE(EMPTY_BAR(c_st));   // early elected release
        MMA_BLOCK(0);
        // ks = 3 (registers only)
        MMA_BLOCK(1);

        if (++c_st == STAGES) { c_st = 0; c_ph ^= 1; }
    }

    // ---- epilogue: f32 (exact integer) * row_scale, float2 stores ----
    const int mbase = m_tile * BM + wm * 32;
    const int nbase = n_tile * BN + wn * 64 + (lane & 3) * 2;
#pragma unroll
    for (int mt = 0; mt < 2; ++mt) {
        const int r0 = mbase + mt * 16 + (lane >> 2);
        const float s0 = g_row_scale[r0];
        const float s1 = g_row_scale[r0 + 8];
        float* o0 = out + (size_t)r0 * N_DIM + nbase;
        float* o1 = o0 + (size_t)8 * N_DIM;
#pragma unroll
        for (int nt = 0; nt < 8; ++nt) {
            float2 v0, v1;
            v0.x = acc[mt][nt][0] * s0;
            v0.y = acc[mt][nt][1] * s0;
            v1.x = acc[mt][nt][2] * s1;
            v1.y = acc[mt][nt][3] * s1;
            *(float2*)(o0 + nt * 8) = v0;
            *(float2*)(o1 + nt * 8) = v1;
        }
    }
#undef PRODUCE_A
#undef PRODUCE_B
#undef LOAD_FRAGS
#undef MMA_BLOCK
#undef FULL_BAR
#undef EMPTY_BAR
}

// ---------------------------------------------------------------------------
// Host launcher — 3 launches: wabs=0, quant_fused=1, gemm=2
// ---------------------------------------------------------------------------
extern "C" void kernel_launch(void* const* d_in, const int* in_sizes, int n_in,
                              void* d_out, int out_size) {
    const float* x = (const float*)d_in[0];
    const float* w = (const float*)d_in[1];
    if (n_in >= 2 && in_sizes[0] == W_ELEMS && in_sizes[1] == X_ELEMS) {
        const float* t = x; x = w; w = t;   // defensive: swapped metadata order
    }
    float* out = (float*)d_out;

    void* p_qw = nullptr;
    void* p_qx = nullptr;
    cudaGetSymbolAddress(&p_qw, g_qw);
    cudaGetSymbolAddress(&p_qx, g_qx);

    cudaFuncSetAttribute(gemm_bf16, cudaFuncAttributeMaxDynamicSharedMemorySize, SMEM_BYTES);

    wabs_partial_kernel<<<1024, 256>>>((const float4*)w, W_ELEMS / 4);
    quant_fused_kernel<<<QW_BLOCKS + M_DIM, 256>>>((const float4*)w, x, W_ELEMS / 4);

    gemm_bf16<<<M_TILES * N_TILES, 256, SMEM_BYTES>>>(
        (const __nv_bfloat16*)p_qx, (const __nv_bfloat16*)p_qw, out);
}